// round 10
// baseline (speedup 1.0000x reference)
#include <cuda_runtime.h>
#include <math.h>

#define BATCH  64
#define ED     2048
#define NH     16
#define HD     128
#define SLOTS  4096
#define NSPLIT 8
#define SPS    (SLOTS / NSPLIT)   // 512 slots per split block
#define CHUNK  64
#define NCHUNK (SPS / CHUNK)      // 8
#define SCQ    2080               // per-quad stride: 512*4 + 32 pad

// ---------------- device scratch (no allocations allowed) ----------------
__device__ float g_part[NSPLIT][BATCH][2304];          // split-K GEMM partials
__device__ float g_q[BATCH][ED];                       // q
__device__ float g_kn[BATCH][HD];                      // new k token
__device__ float g_vn[BATCH][HD];                      // new v token
__device__ float g_pout[BATCH][NSPLIT][NH][HD];        // unnormalized partial attn out
__device__ float g_ml[BATCH][NSPLIT][NH][2];           // per-split (max, sumexp)
__device__ float g_attno[BATCH][ED];                   // attention output (pre-Wo)

// ---------------- GEMM tile core: one 64x64 output tile, K=256 slice ----------------
__device__ __forceinline__ void gemm_tile(const float* __restrict__ Ap,
                                          const float* __restrict__ W,
                                          int N, int colOff, int n0, int split)
{
    __shared__ float as[32][68];   // A tile transposed [kk][m], padded
    __shared__ float ws[32][64];   // W tile [kk][n]

    int t  = threadIdx.x;
    int k0base = split * 256;
    int mg = t >> 4;
    int ng = t & 15;

    float acc[4][4] = {};

    for (int kt = 0; kt < 8; kt++) {
        int k0 = k0base + kt * 32;
        #pragma unroll
        for (int j = 0; j < 8; j++) {
            int idx = t + j * 256;
            int m = idx >> 5, kk = idx & 31;
            as[kk][m] = Ap[m * ED + k0 + kk];
        }
        #pragma unroll
        for (int j = 0; j < 8; j++) {
            int idx = t + j * 256;
            int kk = idx >> 6, n = idx & 63;
            ws[kk][n] = W[(size_t)(k0 + kk) * N + n0 + n];
        }
        __syncthreads();
        #pragma unroll
        for (int kk = 0; kk < 32; kk++) {
            float4 a4 = *(const float4*)&as[kk][mg * 4];
            float4 w4 = *(const float4*)&ws[kk][ng * 4];
            acc[0][0] += a4.x * w4.x; acc[0][1] += a4.x * w4.y;
            acc[0][2] += a4.x * w4.z; acc[0][3] += a4.x * w4.w;
            acc[1][0] += a4.y * w4.x; acc[1][1] += a4.y * w4.y;
            acc[1][2] += a4.y * w4.z; acc[1][3] += a4.y * w4.w;
            acc[2][0] += a4.z * w4.x; acc[2][1] += a4.z * w4.y;
            acc[2][2] += a4.z * w4.z; acc[2][3] += a4.z * w4.w;
            acc[3][0] += a4.w * w4.x; acc[3][1] += a4.w * w4.y;
            acc[3][2] += a4.w * w4.z; acc[3][3] += a4.w * w4.w;
        }
        __syncthreads();
    }

    #pragma unroll
    for (int mi = 0; mi < 4; mi++) {
        int m = mg * 4 + mi;
        float4 v = make_float4(acc[mi][0], acc[mi][1], acc[mi][2], acc[mi][3]);
        *(float4*)&g_part[split][m][colOff + n0 + ng * 4] = v;
    }
}

// ---------------- fused QKV projection: blocks 0-31 Wq, 32-33 Wk, 34-35 Wv ----------------
__global__ __launch_bounds__(256) void qkv_gemm(const float* __restrict__ x,
                                                const float* __restrict__ Wq,
                                                const float* __restrict__ Wk,
                                                const float* __restrict__ Wv)
{
    int bx = blockIdx.x, split = blockIdx.y;
    if (bx < 32)      gemm_tile(x, Wq, 2048, 0,    bx * 64,        split);
    else if (bx < 34) gemm_tile(x, Wk, 128,  2048, (bx - 32) * 64, split);
    else              gemm_tile(x, Wv, 128,  2176, (bx - 34) * 64, split);
}

// ---------------- output projection GEMM (A = g_attno) ----------------
__global__ __launch_bounds__(256) void out_gemm(const float* __restrict__ Wo)
{
    gemm_tile(&g_attno[0][0], Wo, 2048, 0, blockIdx.x * 64, blockIdx.y);
}

// ---------------- reduce split-K partials + bias -> q, k_new, v_new ----------------
__global__ __launch_bounds__(256) void reduce_qkv(const float* __restrict__ bq,
                                                  const float* __restrict__ bk,
                                                  const float* __restrict__ bv)
{
    int b = blockIdx.x;
    for (int c = threadIdx.x; c < 2304; c += 256) {
        float s = 0.f;
        #pragma unroll
        for (int k = 0; k < NSPLIT; k++) s += g_part[k][b][c];
        if (c < 2048)       g_q[b][c]         = s + bq[c];
        else if (c < 2176)  g_kn[b][c - 2048] = s + bk[c - 2048];
        else                g_vn[b][c - 2176] = s + bv[c - 2176];
    }
}

// ---------------- reduce split-K partials + bias -> final output ----------------
__global__ __launch_bounds__(256) void reduce_out(const float* __restrict__ bo,
                                                  float* __restrict__ out)
{
    int b = blockIdx.x;
    for (int c = threadIdx.x; c < 2048; c += 256) {
        float s = 0.f;
        #pragma unroll
        for (int k = 0; k < NSPLIT; k++) s += g_part[k][b][c];
        out[b * 2048 + c] = s + bo[c];
    }
}

// ---------------- flash-decode attention (fp32, split-S, head-quad layout) ----------------
// grid: (NSPLIT, BATCH), 256 threads (8 warps).
// Warp role: (head-quad hq = wid>>1, slot-half sh = wid&1).
//   Phase A: thread = 4 heads x 1 slot. Each K float4 read by only 4 warps;
//            scores stored interleaved scq[quad][slot][4] via one STS.128.
//   Phase C: thread = 4 heads x 4 dims. Probs arrive as one LDS.128 broadcast;
//            each V float4 read by 4 warps. Slot-halves combined via qs buffer.
// Paged scatter (slot == cache_positions[b] -> k_new/v_new) folded into the
// prefetch predicate; inputs never modified (graph-replay safe).
extern "C" __global__ __launch_bounds__(256) void attn_kernel(
    const float* __restrict__ kc, const float* __restrict__ vc,
    const int* __restrict__ cpos)
{
    extern __shared__ float smf[];
    float* qs = smf;                 // 2048 floats (scaled q; reused for Phase C combine)
    float* kv = smf + 2048;          // 64*132 = 8448 floats (K or V chunk, padded)
    float* sc = smf + 2048 + 8448;   // 4*2080 = 8320 floats (interleaved scores [quad][slot][4])

    int b = blockIdx.y, split = blockIdx.x;
    int t = threadIdx.x;
    int pos = cpos[b];
    const float scale = 0.08838834764831845f;  // 1/sqrt(128)

    // load q (scaled)
    for (int j = t; j < ED / 4; j += 256) {
        float4 v = *(const float4*)&g_q[b][j * 4];
        v.x *= scale; v.y *= scale; v.z *= scale; v.w *= scale;
        *(float4*)&qs[j * 4] = v;
    }

    int wid  = t >> 5;
    int lane = t & 31;
    int hq   = wid >> 1;          // head quad 0..3 -> heads 4hq..4hq+3 (warp-uniform)
    int sh   = wid & 1;           // slot half 0..1 (warp-uniform)

    float4 pre[8];

    #define PREFETCH(CACHE, NEWTOK, CH)                                          \
        {                                                                        \
            int base_ = split * SPS + (CH) * CHUNK;                              \
            const float* src_ = (CACHE) + ((size_t)b * SLOTS + base_) * HD;      \
            _Pragma("unroll")                                                    \
            for (int r = 0; r < 8; r++) {                                        \
                int j_ = t + r * 256;                                            \
                int s_ = j_ >> 5, i_ = j_ & 31;                                  \
                pre[r] = (base_ + s_ == pos)                                     \
                       ? *(const float4*)&(NEWTOK)[b][i_ * 4]                    \
                       : *(const float4*)&src_[s_ * HD + i_ * 4];                \
            }                                                                    \
        }

    #define STORE_PRE()                                                          \
        {                                                                        \
            _Pragma("unroll")                                                    \
            for (int r = 0; r < 8; r++) {                                        \
                int j_ = t + r * 256;                                            \
                int s_ = j_ >> 5, i_ = j_ & 31;                                  \
                *(float4*)&kv[s_ * 132 + i_ * 4] = pre[r];                       \
            }                                                                    \
        }

    // ---- Phase A: scores (4 heads x 1 slot per thread) ----
    {
        int ts = sh * 32 + lane;    // slot within chunk 0..63
        PREFETCH(kc, g_kn, 0)
        __syncthreads();   // qs visible
        for (int ch = 0; ch < NCHUNK; ch++) {
            STORE_PRE()
            __syncthreads();
            if (ch + 1 < NCHUNK) PREFETCH(kc, g_kn, ch + 1)

            float d0 = 0.f, d1 = 0.f, d2 = 0.f, d3 = 0.f;
            #pragma unroll
            for (int i = 0; i < 32; i++) {
                float4 k4 = *(const float4*)&kv[ts * 132 + i * 4];
                float4 q0 = *(const float4*)&qs[(4 * hq    ) * HD + i * 4];  // broadcast
                float4 q1 = *(const float4*)&qs[(4 * hq + 1) * HD + i * 4];
                float4 q2 = *(const float4*)&qs[(4 * hq + 2) * HD + i * 4];
                float4 q3 = *(const float4*)&qs[(4 * hq + 3) * HD + i * 4];
                d0 += q0.x * k4.x + q0.y * k4.y + q0.z * k4.z + q0.w * k4.w;
                d1 += q1.x * k4.x + q1.y * k4.y + q1.z * k4.z + q1.w * k4.w;
                d2 += q2.x * k4.x + q2.y * k4.y + q2.z * k4.z + q2.w * k4.w;
                d3 += q3.x * k4.x + q3.y * k4.y + q3.z * k4.z + q3.w * k4.w;
            }
            *(float4*)&sc[hq * SCQ + (ch * CHUNK + ts) * 4] = make_float4(d0, d1, d2, d3);
            __syncthreads();
        }
    }

    // ---- Phase B: softmax over this split's SPS slots (per head, interleaved layout) ----
    {
        int h  = t >> 4;              // head 0..15
        int sl = t & 15;
        int qd = h >> 2, p4 = h & 3;  // quad, pos-in-quad
        float m = -1e30f;
        for (int j = sl; j < SPS; j += 16) m = fmaxf(m, sc[qd * SCQ + j * 4 + p4]);
        #pragma unroll
        for (int msk = 8; msk >= 1; msk >>= 1)
            m = fmaxf(m, __shfl_xor_sync(0xffffffffu, m, msk));
        float l = 0.f;
        for (int j = sl; j < SPS; j += 16) {
            float e = __expf(sc[qd * SCQ + j * 4 + p4] - m);
            sc[qd * SCQ + j * 4 + p4] = e;
            l += e;
        }
        #pragma unroll
        for (int msk = 8; msk >= 1; msk >>= 1)
            l += __shfl_xor_sync(0xffffffffu, l, msk);
        if (sl == 0) {
            g_ml[b][split][h][0] = m;
            g_ml[b][split][h][1] = l;
        }
    }
    __syncthreads();

    // ---- Phase C: p @ V (4 heads x 4 dims per thread; slot-halves combined at end) ----
    {
        int dl = lane;                 // dims dl*4..dl*4+3
        float4 a0 = make_float4(0.f, 0.f, 0.f, 0.f);
        float4 a1 = a0, a2 = a0, a3 = a0;

        PREFETCH(vc, g_vn, 0)
        for (int ch = 0; ch < NCHUNK; ch++) {
            STORE_PRE()
            __syncthreads();
            if (ch + 1 < NCHUNK) PREFETCH(vc, g_vn, ch + 1)

            #pragma unroll 8
            for (int s = 0; s < 32; s++) {
                int slot = sh * 32 + s;
                float4 p = *(const float4*)&sc[hq * SCQ + (ch * CHUNK + slot) * 4]; // broadcast
                float4 v = *(const float4*)&kv[slot * 132 + dl * 4];
                a0.x += p.x * v.x; a0.y += p.x * v.y; a0.z += p.x * v.z; a0.w += p.x * v.w;
                a1.x += p.y * v.x; a1.y += p.y * v.y; a1.z += p.y * v.z; a1.w += p.y * v.w;
                a2.x += p.z * v.x; a2.y += p.z * v.y; a2.z += p.z * v.z; a2.w += p.z * v.w;
                a3.x += p.w * v.x; a3.y += p.w * v.y; a3.z += p.w * v.z; a3.w += p.w * v.w;
            }
            __syncthreads();
        }

        // combine slot-halves via qs buffer (q no longer needed)
        if (sh == 1) {
            *(float4*)&qs[hq * 512 +   0 + dl * 4] = a0;
            *(float4*)&qs[hq * 512 + 128 + dl * 4] = a1;
            *(float4*)&qs[hq * 512 + 256 + dl * 4] = a2;
            *(float4*)&qs[hq * 512 + 384 + dl * 4] = a3;
        }
        __syncthreads();
        if (sh == 0) {
            float4 o0 = *(const float4*)&qs[hq * 512 +   0 + dl * 4];
            float4 o1 = *(const float4*)&qs[hq * 512 + 128 + dl * 4];
            float4 o2 = *(const float4*)&qs[hq * 512 + 256 + dl * 4];
            float4 o3 = *(const float4*)&qs[hq * 512 + 384 + dl * 4];
            a0.x += o0.x; a0.y += o0.y; a0.z += o0.z; a0.w += o0.w;
            a1.x += o1.x; a1.y += o1.y; a1.z += o1.z; a1.w += o1.w;
            a2.x += o2.x; a2.y += o2.y; a2.z += o2.z; a2.w += o2.w;
            a3.x += o3.x; a3.y += o3.y; a3.z += o3.z; a3.w += o3.w;
            *(float4*)&g_pout[b][split][4 * hq    ][dl * 4] = a0;
            *(float4*)&g_pout[b][split][4 * hq + 1][dl * 4] = a1;
            *(float4*)&g_pout[b][split][4 * hq + 2][dl * 4] = a2;
            *(float4*)&g_pout[b][split][4 * hq + 3][dl * 4] = a3;
        }
    }

    #undef PREFETCH
    #undef STORE_PRE
}

// ---------------- combine split-S partials (log-sum-exp merge) ----------------
__global__ __launch_bounds__(256) void combine_kernel()
{
    int b = blockIdx.x, t = threadIdx.x;
    __shared__ float fac[NH][NSPLIT];
    __shared__ float invl[NH];
    if (t < NH) {
        float M = -1e30f;
        for (int s = 0; s < NSPLIT; s++) M = fmaxf(M, g_ml[b][s][t][0]);
        float L = 0.f;
        for (int s = 0; s < NSPLIT; s++) {
            float f = __expf(g_ml[b][s][t][0] - M);
            fac[t][s] = f;
            L += g_ml[b][s][t][1] * f;
        }
        invl[t] = 1.0f / L;
    }
    __syncthreads();
    for (int o = t; o < ED; o += 256) {
        int h = o >> 7, d = o & 127;
        float sum = 0.f;
        #pragma unroll
        for (int s = 0; s < NSPLIT; s++) sum += g_pout[b][s][h][d] * fac[h][s];
        g_attno[b][o] = sum * invl[h];
    }
}

// ---------------- launch ----------------
extern "C" void kernel_launch(void* const* d_in, const int* in_sizes, int n_in,
                              void* d_out, int out_size)
{
    (void)in_sizes; (void)n_in; (void)out_size;
    const float* x    = (const float*)d_in[0];
    const float* kc   = (const float*)d_in[1];
    const float* vc   = (const float*)d_in[2];
    const int*   cpos = (const int*)  d_in[3];
    const float* Wq   = (const float*)d_in[4];
    const float* bq   = (const float*)d_in[5];
    const float* Wk   = (const float*)d_in[6];
    const float* bk   = (const float*)d_in[7];
    const float* Wv   = (const float*)d_in[8];
    const float* bv   = (const float*)d_in[9];
    const float* Wo   = (const float*)d_in[10];
    const float* bo   = (const float*)d_in[11];
    float* out = (float*)d_out;

    // Fused QKV projections (split-K x8, one launch)
    qkv_gemm<<<dim3(36, NSPLIT), 256>>>(x, Wq, Wk, Wv);
    reduce_qkv<<<BATCH, 256>>>(bq, bk, bv);

    // Attention (split-S flash decode)
    size_t smem = (size_t)(2048 + 8448 + 4 * SCQ) * sizeof(float);  // 75264 B
    cudaFuncSetAttribute((const void*)attn_kernel,
                         cudaFuncAttributeMaxDynamicSharedMemorySize, (int)smem);
    attn_kernel<<<dim3(NSPLIT, BATCH), 256, smem>>>(kc, vc, cpos);
    combine_kernel<<<BATCH, 256>>>();

    // Output projection
    out_gemm<<<dim3(32, NSPLIT), 256>>>(Wo);
    reduce_out<<<BATCH, 256>>>(bo, out);
}

// round 11
// speedup vs baseline: 1.1095x; 1.1095x over previous
#include <cuda_runtime.h>
#include <math.h>

#define BATCH  64
#define ED     2048
#define NH     16
#define HD     128
#define SLOTS  4096
#define NSPLIT 8
#define SPS    (SLOTS / NSPLIT)   // 512 slots per split block
#define CHUNK  64
#define NCHUNK (SPS / CHUNK)      // 8
#define SCQ    2080               // per-quad stride: 512*4 + 32 pad

// ---------------- device scratch (no allocations allowed) ----------------
__device__ float g_part[NSPLIT][BATCH][2304];          // split-K GEMM partials
__device__ float g_q[BATCH][ED];                       // q
__device__ float g_kn[BATCH][HD];                      // new k token
__device__ float g_vn[BATCH][HD];                      // new v token
__device__ float g_pout[BATCH][NSPLIT][NH][HD];        // unnormalized partial attn out
__device__ float g_ml[BATCH][NSPLIT][NH][2];           // per-split (max, sumexp)
__device__ float g_attno[BATCH][ED];                   // attention output (pre-Wo)

// ---------------- GEMM tile core: one 64x64 output tile, K=256 slice ----------------
// Register double-buffered: kt+1's tiles are loaded into registers during kt's FFMAs.
__device__ __forceinline__ void gemm_tile(const float* __restrict__ Ap,
                                          const float* __restrict__ W,
                                          int N, int colOff, int n0, int split)
{
    __shared__ float as[32][68];   // A tile transposed [kk][m], padded
    __shared__ float ws[32][64];   // W tile [kk][n]

    int t  = threadIdx.x;
    int k0base = split * 256;
    int mg = t >> 4;
    int ng = t & 15;

    float acc[4][4] = {};
    float a_pre[8], w_pre[8];

    // prefetch kt = 0
    {
        int k0 = k0base;
        #pragma unroll
        for (int j = 0; j < 8; j++) {
            int idx = t + j * 256;
            int m = idx >> 5, kk = idx & 31;
            a_pre[j] = Ap[m * ED + k0 + kk];
        }
        #pragma unroll
        for (int j = 0; j < 8; j++) {
            int idx = t + j * 256;
            int kk = idx >> 6, n = idx & 63;
            w_pre[j] = W[(size_t)(k0 + kk) * N + n0 + n];
        }
    }

    for (int kt = 0; kt < 8; kt++) {
        __syncthreads();   // prior compute done reading smem
        #pragma unroll
        for (int j = 0; j < 8; j++) {
            int idx = t + j * 256;
            int m = idx >> 5, kk = idx & 31;
            as[kk][m] = a_pre[j];
        }
        #pragma unroll
        for (int j = 0; j < 8; j++) {
            int idx = t + j * 256;
            int kk = idx >> 6, n = idx & 63;
            ws[kk][n] = w_pre[j];
        }
        __syncthreads();

        if (kt + 1 < 8) {   // LDGs in flight over the FFMA block
            int k0 = k0base + (kt + 1) * 32;
            #pragma unroll
            for (int j = 0; j < 8; j++) {
                int idx = t + j * 256;
                int m = idx >> 5, kk = idx & 31;
                a_pre[j] = Ap[m * ED + k0 + kk];
            }
            #pragma unroll
            for (int j = 0; j < 8; j++) {
                int idx = t + j * 256;
                int kk = idx >> 6, n = idx & 63;
                w_pre[j] = W[(size_t)(k0 + kk) * N + n0 + n];
            }
        }

        #pragma unroll
        for (int kk = 0; kk < 32; kk++) {
            float4 a4 = *(const float4*)&as[kk][mg * 4];
            float4 w4 = *(const float4*)&ws[kk][ng * 4];
            acc[0][0] += a4.x * w4.x; acc[0][1] += a4.x * w4.y;
            acc[0][2] += a4.x * w4.z; acc[0][3] += a4.x * w4.w;
            acc[1][0] += a4.y * w4.x; acc[1][1] += a4.y * w4.y;
            acc[1][2] += a4.y * w4.z; acc[1][3] += a4.y * w4.w;
            acc[2][0] += a4.z * w4.x; acc[2][1] += a4.z * w4.y;
            acc[2][2] += a4.z * w4.z; acc[2][3] += a4.z * w4.w;
            acc[3][0] += a4.w * w4.x; acc[3][1] += a4.w * w4.y;
            acc[3][2] += a4.w * w4.z; acc[3][3] += a4.w * w4.w;
        }
    }

    #pragma unroll
    for (int mi = 0; mi < 4; mi++) {
        int m = mg * 4 + mi;
        float4 v = make_float4(acc[mi][0], acc[mi][1], acc[mi][2], acc[mi][3]);
        *(float4*)&g_part[split][m][colOff + n0 + ng * 4] = v;
    }
}

// ---------------- fused QKV projection: blocks 0-31 Wq, 32-33 Wk, 34-35 Wv ----------------
__global__ __launch_bounds__(256) void qkv_gemm(const float* __restrict__ x,
                                                const float* __restrict__ Wq,
                                                const float* __restrict__ Wk,
                                                const float* __restrict__ Wv)
{
    int bx = blockIdx.x, split = blockIdx.y;
    if (bx < 32)      gemm_tile(x, Wq, 2048, 0,    bx * 64,        split);
    else if (bx < 34) gemm_tile(x, Wk, 128,  2048, (bx - 32) * 64, split);
    else              gemm_tile(x, Wv, 128,  2176, (bx - 34) * 64, split);
}

// ---------------- output projection GEMM (A = g_attno) ----------------
__global__ __launch_bounds__(256) void out_gemm(const float* __restrict__ Wo)
{
    gemm_tile(&g_attno[0][0], Wo, 2048, 0, blockIdx.x * 64, blockIdx.y);
}

// ---------------- reduce split-K partials + bias -> q, k_new, v_new ----------------
// grid (BATCH, 9): block handles 256 of the 2304 columns (full-chip, MLP-8 loads)
__global__ __launch_bounds__(256) void reduce_qkv(const float* __restrict__ bq,
                                                  const float* __restrict__ bk,
                                                  const float* __restrict__ bv)
{
    int b = blockIdx.x;
    int c = blockIdx.y * 256 + threadIdx.x;
    float s = 0.f;
    #pragma unroll
    for (int k = 0; k < NSPLIT; k++) s += g_part[k][b][c];
    if (c < 2048)       g_q[b][c]         = s + bq[c];
    else if (c < 2176)  g_kn[b][c - 2048] = s + bk[c - 2048];
    else                g_vn[b][c - 2176] = s + bv[c - 2176];
}

// ---------------- reduce split-K partials + bias -> final output ----------------
// grid (BATCH, 8)
__global__ __launch_bounds__(256) void reduce_out(const float* __restrict__ bo,
                                                  float* __restrict__ out)
{
    int b = blockIdx.x;
    int c = blockIdx.y * 256 + threadIdx.x;
    float s = 0.f;
    #pragma unroll
    for (int k = 0; k < NSPLIT; k++) s += g_part[k][b][c];
    out[b * 2048 + c] = s + bo[c];
}

// ---------------- flash-decode attention (fp32, split-S, head-quad layout) ----------------
// grid: (NSPLIT, BATCH), 256 threads (8 warps). UNCHANGED from the passing R9 kernel.
extern "C" __global__ __launch_bounds__(256) void attn_kernel(
    const float* __restrict__ kc, const float* __restrict__ vc,
    const int* __restrict__ cpos)
{
    extern __shared__ float smf[];
    float* qs = smf;                 // 2048 floats (scaled q; reused for Phase C combine)
    float* kv = smf + 2048;          // 64*132 = 8448 floats (K or V chunk, padded)
    float* sc = smf + 2048 + 8448;   // 4*2080 = 8320 floats (interleaved scores [quad][slot][4])

    int b = blockIdx.y, split = blockIdx.x;
    int t = threadIdx.x;
    int pos = cpos[b];
    const float scale = 0.08838834764831845f;  // 1/sqrt(128)

    for (int j = t; j < ED / 4; j += 256) {
        float4 v = *(const float4*)&g_q[b][j * 4];
        v.x *= scale; v.y *= scale; v.z *= scale; v.w *= scale;
        *(float4*)&qs[j * 4] = v;
    }

    int wid  = t >> 5;
    int lane = t & 31;
    int hq   = wid >> 1;
    int sh   = wid & 1;

    float4 pre[8];

    #define PREFETCH(CACHE, NEWTOK, CH)                                          \
        {                                                                        \
            int base_ = split * SPS + (CH) * CHUNK;                              \
            const float* src_ = (CACHE) + ((size_t)b * SLOTS + base_) * HD;      \
            _Pragma("unroll")                                                    \
            for (int r = 0; r < 8; r++) {                                        \
                int j_ = t + r * 256;                                            \
                int s_ = j_ >> 5, i_ = j_ & 31;                                  \
                pre[r] = (base_ + s_ == pos)                                     \
                       ? *(const float4*)&(NEWTOK)[b][i_ * 4]                    \
                       : *(const float4*)&src_[s_ * HD + i_ * 4];                \
            }                                                                    \
        }

    #define STORE_PRE()                                                          \
        {                                                                        \
            _Pragma("unroll")                                                    \
            for (int r = 0; r < 8; r++) {                                        \
                int j_ = t + r * 256;                                            \
                int s_ = j_ >> 5, i_ = j_ & 31;                                  \
                *(float4*)&kv[s_ * 132 + i_ * 4] = pre[r];                       \
            }                                                                    \
        }

    // ---- Phase A: scores (4 heads x 1 slot per thread) ----
    {
        int ts = sh * 32 + lane;
        PREFETCH(kc, g_kn, 0)
        __syncthreads();
        for (int ch = 0; ch < NCHUNK; ch++) {
            STORE_PRE()
            __syncthreads();
            if (ch + 1 < NCHUNK) PREFETCH(kc, g_kn, ch + 1)

            float d0 = 0.f, d1 = 0.f, d2 = 0.f, d3 = 0.f;
            #pragma unroll
            for (int i = 0; i < 32; i++) {
                float4 k4 = *(const float4*)&kv[ts * 132 + i * 4];
                float4 q0 = *(const float4*)&qs[(4 * hq    ) * HD + i * 4];
                float4 q1 = *(const float4*)&qs[(4 * hq + 1) * HD + i * 4];
                float4 q2 = *(const float4*)&qs[(4 * hq + 2) * HD + i * 4];
                float4 q3 = *(const float4*)&qs[(4 * hq + 3) * HD + i * 4];
                d0 += q0.x * k4.x + q0.y * k4.y + q0.z * k4.z + q0.w * k4.w;
                d1 += q1.x * k4.x + q1.y * k4.y + q1.z * k4.z + q1.w * k4.w;
                d2 += q2.x * k4.x + q2.y * k4.y + q2.z * k4.z + q2.w * k4.w;
                d3 += q3.x * k4.x + q3.y * k4.y + q3.z * k4.z + q3.w * k4.w;
            }
            *(float4*)&sc[hq * SCQ + (ch * CHUNK + ts) * 4] = make_float4(d0, d1, d2, d3);
            __syncthreads();
        }
    }

    // ---- Phase B: softmax (per head, interleaved layout) ----
    {
        int h  = t >> 4;
        int sl = t & 15;
        int qd = h >> 2, p4 = h & 3;
        float m = -1e30f;
        for (int j = sl; j < SPS; j += 16) m = fmaxf(m, sc[qd * SCQ + j * 4 + p4]);
        #pragma unroll
        for (int msk = 8; msk >= 1; msk >>= 1)
            m = fmaxf(m, __shfl_xor_sync(0xffffffffu, m, msk));
        float l = 0.f;
        for (int j = sl; j < SPS; j += 16) {
            float e = __expf(sc[qd * SCQ + j * 4 + p4] - m);
            sc[qd * SCQ + j * 4 + p4] = e;
            l += e;
        }
        #pragma unroll
        for (int msk = 8; msk >= 1; msk >>= 1)
            l += __shfl_xor_sync(0xffffffffu, l, msk);
        if (sl == 0) {
            g_ml[b][split][h][0] = m;
            g_ml[b][split][h][1] = l;
        }
    }
    __syncthreads();

    // ---- Phase C: p @ V (4 heads x 4 dims per thread; slot-halves combined at end) ----
    {
        int dl = lane;
        float4 a0 = make_float4(0.f, 0.f, 0.f, 0.f);
        float4 a1 = a0, a2 = a0, a3 = a0;

        PREFETCH(vc, g_vn, 0)
        for (int ch = 0; ch < NCHUNK; ch++) {
            STORE_PRE()
            __syncthreads();
            if (ch + 1 < NCHUNK) PREFETCH(vc, g_vn, ch + 1)

            #pragma unroll 8
            for (int s = 0; s < 32; s++) {
                int slot = sh * 32 + s;
                float4 p = *(const float4*)&sc[hq * SCQ + (ch * CHUNK + slot) * 4];
                float4 v = *(const float4*)&kv[slot * 132 + dl * 4];
                a0.x += p.x * v.x; a0.y += p.x * v.y; a0.z += p.x * v.z; a0.w += p.x * v.w;
                a1.x += p.y * v.x; a1.y += p.y * v.y; a1.z += p.y * v.z; a1.w += p.y * v.w;
                a2.x += p.z * v.x; a2.y += p.z * v.y; a2.z += p.z * v.z; a2.w += p.z * v.w;
                a3.x += p.w * v.x; a3.y += p.w * v.y; a3.z += p.w * v.z; a3.w += p.w * v.w;
            }
            __syncthreads();
        }

        if (sh == 1) {
            *(float4*)&qs[hq * 512 +   0 + dl * 4] = a0;
            *(float4*)&qs[hq * 512 + 128 + dl * 4] = a1;
            *(float4*)&qs[hq * 512 + 256 + dl * 4] = a2;
            *(float4*)&qs[hq * 512 + 384 + dl * 4] = a3;
        }
        __syncthreads();
        if (sh == 0) {
            float4 o0 = *(const float4*)&qs[hq * 512 +   0 + dl * 4];
            float4 o1 = *(const float4*)&qs[hq * 512 + 128 + dl * 4];
            float4 o2 = *(const float4*)&qs[hq * 512 + 256 + dl * 4];
            float4 o3 = *(const float4*)&qs[hq * 512 + 384 + dl * 4];
            a0.x += o0.x; a0.y += o0.y; a0.z += o0.z; a0.w += o0.w;
            a1.x += o1.x; a1.y += o1.y; a1.z += o1.z; a1.w += o1.w;
            a2.x += o2.x; a2.y += o2.y; a2.z += o2.z; a2.w += o2.w;
            a3.x += o3.x; a3.y += o3.y; a3.z += o3.z; a3.w += o3.w;
            *(float4*)&g_pout[b][split][4 * hq    ][dl * 4] = a0;
            *(float4*)&g_pout[b][split][4 * hq + 1][dl * 4] = a1;
            *(float4*)&g_pout[b][split][4 * hq + 2][dl * 4] = a2;
            *(float4*)&g_pout[b][split][4 * hq + 3][dl * 4] = a3;
        }
    }

    #undef PREFETCH
    #undef STORE_PRE
}

// ---------------- combine split-S partials (log-sum-exp merge) ----------------
// grid (BATCH, 8): block handles 256 of the 2048 outputs (full-chip)
__global__ __launch_bounds__(256) void combine_kernel()
{
    int b = blockIdx.x, t = threadIdx.x;
    __shared__ float fac[NH][NSPLIT];
    __shared__ float invl[NH];
    if (t < NH) {
        float M = -1e30f;
        for (int s = 0; s < NSPLIT; s++) M = fmaxf(M, g_ml[b][s][t][0]);
        float L = 0.f;
        for (int s = 0; s < NSPLIT; s++) {
            float f = __expf(g_ml[b][s][t][0] - M);
            fac[t][s] = f;
            L += g_ml[b][s][t][1] * f;
        }
        invl[t] = 1.0f / L;
    }
    __syncthreads();
    int o = blockIdx.y * 256 + t;
    int h = o >> 7, d = o & 127;
    float sum = 0.f;
    #pragma unroll
    for (int s = 0; s < NSPLIT; s++) sum += g_pout[b][s][h][d] * fac[h][s];
    g_attno[b][o] = sum * invl[h];
}

// ---------------- launch ----------------
extern "C" void kernel_launch(void* const* d_in, const int* in_sizes, int n_in,
                              void* d_out, int out_size)
{
    (void)in_sizes; (void)n_in; (void)out_size;
    const float* x    = (const float*)d_in[0];
    const float* kc   = (const float*)d_in[1];
    const float* vc   = (const float*)d_in[2];
    const int*   cpos = (const int*)  d_in[3];
    const float* Wq   = (const float*)d_in[4];
    const float* bq   = (const float*)d_in[5];
    const float* Wk   = (const float*)d_in[6];
    const float* bk   = (const float*)d_in[7];
    const float* Wv   = (const float*)d_in[8];
    const float* bv   = (const float*)d_in[9];
    const float* Wo   = (const float*)d_in[10];
    const float* bo   = (const float*)d_in[11];
    float* out = (float*)d_out;

    // Fused QKV projections (split-K x8, one launch)
    qkv_gemm<<<dim3(36, NSPLIT), 256>>>(x, Wq, Wk, Wv);
    reduce_qkv<<<dim3(BATCH, 9), 256>>>(bq, bk, bv);

    // Attention (split-S flash decode)
    size_t smem = (size_t)(2048 + 8448 + 4 * SCQ) * sizeof(float);  // 75264 B
    cudaFuncSetAttribute((const void*)attn_kernel,
                         cudaFuncAttributeMaxDynamicSharedMemorySize, (int)smem);
    attn_kernel<<<dim3(NSPLIT, BATCH), 256, smem>>>(kc, vc, cpos);
    combine_kernel<<<dim3(BATCH, 8), 256>>>();

    // Output projection
    out_gemm<<<dim3(32, NSPLIT), 256>>>(Wo);
    reduce_out<<<dim3(BATCH, 8), 256>>>(bo, out);
}